// round 1
// baseline (speedup 1.0000x reference)
#include <cuda_runtime.h>
#include <math.h>

#define NN 50000
#define EE 800000
#define HID 128
#define GG 128
#define LAT 32
#define NEG 0.2f

// ---------------- scratch (static device memory; no allocations) ----------------
__device__ float g_h[NN * HID];      // linear output of current layer (pre-bias)
__device__ float g_y[NN * HID];      // node features (layer output)
__device__ float g_as[NN * 4];       // alpha_src per node/head
__device__ float g_ad[NN * 4];       // alpha_dst per node/head
__device__ int   g_deg[NN];
__device__ int   g_rowoff[NN + 1];
__device__ int   g_cur[NN];
__device__ int   g_csr[EE + NN];     // src node id per incoming edge, grouped by dst
__device__ float g_pool[GG * HID];

// ---------------- CSR build ----------------
__global__ void init_kernel() {
    int i = blockIdx.x * blockDim.x + threadIdx.x;
    if (i < NN) g_deg[i] = 1;                 // self loop
    if (i < GG * HID) g_pool[i] = 0.0f;
}

__global__ void hist_kernel(const int* __restrict__ dst) {
    int i = blockIdx.x * blockDim.x + threadIdx.x;
    if (i < EE) atomicAdd(&g_deg[dst[i]], 1);
}

__global__ void scan_kernel() {
    __shared__ int sums[1024];
    const int T = 1024;
    int t = threadIdx.x;
    const int chunk = (NN + T - 1) / T;
    int start = t * chunk;
    int end = min(start + chunk, NN);
    int s = 0;
    for (int i = start; i < end; i++) s += g_deg[i];
    sums[t] = s;
    __syncthreads();
    // inclusive scan (Hillis-Steele)
    for (int off = 1; off < T; off <<= 1) {
        int v = 0;
        if (t >= off) v = sums[t - off];
        __syncthreads();
        if (t >= off) sums[t] += v;
        __syncthreads();
    }
    int base = (t == 0) ? 0 : sums[t - 1];
    for (int i = start; i < end; i++) {
        g_rowoff[i] = base;
        g_cur[i] = base;
        base += g_deg[i];
    }
    if (t == 0) g_rowoff[NN] = sums[T - 1];
}

__global__ void scatter_kernel(const int* __restrict__ src, const int* __restrict__ dst) {
    int i = blockIdx.x * blockDim.x + threadIdx.x;
    if (i < EE) {
        int d = dst[i];
        int pos = atomicAdd(&g_cur[d], 1);
        g_csr[pos] = src[i];
    } else if (i < EE + NN) {
        int n = i - EE;
        int pos = atomicAdd(&g_cur[n], 1);
        g_csr[pos] = n;  // self loop
    }
}

// ---------------- GEMM: Out[n, 128] = X[n, K] @ W[K, 128] ----------------
// Block: 256 threads, tile 32 rows x 128 cols, K chunked by 64 (static smem).
__global__ __launch_bounds__(256) void gemm_kernel(
    const float* __restrict__ X, const float* __restrict__ W,
    float* __restrict__ Out, int nrows, int K)
{
    __shared__ float Ws[64 * 128];     // 32 KB
    __shared__ float xs[32 * 68];      // padded stride 68, ~8.5 KB
    int tid = threadIdx.x;
    int ty = tid >> 3;       // 0..31 : row within tile
    int tx = tid & 7;        // 0..7  : col group; cols tx*4 + i*32
    int row0 = blockIdx.x * 32;
    int row = row0 + ty;

    float4 acc[4];
#pragma unroll
    for (int i = 0; i < 4; i++) acc[i] = make_float4(0.f, 0.f, 0.f, 0.f);

    for (int k0 = 0; k0 < K; k0 += 64) {
        // load W chunk [64][128], contiguous
        const float4* Wg = (const float4*)(W + k0 * 128);
        float4* Wsv = (float4*)Ws;
        for (int i = tid; i < 64 * 128 / 4; i += 256) Wsv[i] = Wg[i];
        // load x tile [32][64] -> xs padded
        for (int i = tid; i < 32 * 64; i += 256) {
            int r = i >> 6, k = i & 63;
            int gr = row0 + r;
            xs[r * 68 + k] = (gr < nrows) ? X[gr * K + k0 + k] : 0.0f;
        }
        __syncthreads();
#pragma unroll 4
        for (int k = 0; k < 64; k++) {
            float xv = xs[ty * 68 + k];
            const float* wr = Ws + k * 128 + tx * 4;
#pragma unroll
            for (int i = 0; i < 4; i++) {
                float4 w = *(const float4*)(wr + i * 32);
                acc[i].x = fmaf(xv, w.x, acc[i].x);
                acc[i].y = fmaf(xv, w.y, acc[i].y);
                acc[i].z = fmaf(xv, w.z, acc[i].z);
                acc[i].w = fmaf(xv, w.w, acc[i].w);
            }
        }
        __syncthreads();
    }
    if (row < nrows) {
        float4* o = (float4*)(Out + row * 128);
#pragma unroll
        for (int i = 0; i < 4; i++) o[i * 8 + tx] = acc[i];
    }
}

// ---------------- alpha: as[n,h] = <h[n,h,:], a_src[h,:]>, ad likewise ----------------
__global__ void alpha_kernel(const float* __restrict__ hbuf,
                             const float* __restrict__ a_src,
                             const float* __restrict__ a_dst)
{
    int w = (blockIdx.x * blockDim.x + threadIdx.x) >> 5;
    if (w >= NN) return;
    int lane = threadIdx.x & 31;
#pragma unroll
    for (int h = 0; h < 4; h++) {
        float v = hbuf[w * 128 + h * 32 + lane];
        float s1 = v * a_src[h * 32 + lane];
        float s2 = v * a_dst[h * 32 + lane];
#pragma unroll
        for (int off = 16; off; off >>= 1) {
            s1 += __shfl_xor_sync(0xffffffffu, s1, off);
            s2 += __shfl_xor_sync(0xffffffffu, s2, off);
        }
        if (lane == 0) {
            g_as[w * 4 + h] = s1;
            g_ad[w * 4 + h] = s2;
        }
    }
}

// ---------------- aggregation: one warp per dst node, online softmax ----------------
__global__ __launch_bounds__(256) void agg_kernel(
    const float* __restrict__ hbuf, const float* __restrict__ bias,
    float* __restrict__ outbuf)
{
    int n = (blockIdx.x * blockDim.x + threadIdx.x) >> 5;
    if (n >= NN) return;
    int lane = threadIdx.x & 31;

    float4 adv = *(const float4*)&g_ad[n * 4];
    float ad_[4] = {adv.x, adv.y, adv.z, adv.w};

    float m[4], s[4], acc[4];
#pragma unroll
    for (int h = 0; h < 4; h++) { m[h] = -1e30f; s[h] = 0.f; acc[h] = 0.f; }

    int beg = g_rowoff[n], end = g_rowoff[n + 1];
    for (int p = beg; p < end; p += 32) {
        int cnt = min(32, end - p);
        int src_l = (lane < cnt) ? __ldg(&g_csr[p + lane]) : 0;
        for (int j = 0; j < cnt; j++) {
            int src = __shfl_sync(0xffffffffu, src_l, j);
            float4 asv = __ldg((const float4*)&g_as[src * 4]);
            float as_[4] = {asv.x, asv.y, asv.z, asv.w};
            const float* hrow = hbuf + src * 128 + lane;
#pragma unroll
            for (int h = 0; h < 4; h++) {
                float e = as_[h] + ad_[h];
                e = fmaxf(e, NEG * e);                  // leaky_relu
                float hv = __ldg(hrow + h * 32);
                if (e > m[h]) {                         // warp-uniform branch
                    float sc = __expf(m[h] - e);        // 0 on first edge
                    s[h] = fmaf(s[h], sc, 1.0f);
                    acc[h] = fmaf(acc[h], sc, hv);
                    m[h] = e;
                } else {
                    float pp = __expf(e - m[h]);
                    s[h] += pp;
                    acc[h] = fmaf(pp, hv, acc[h]);
                }
            }
        }
    }
#pragma unroll
    for (int h = 0; h < 4; h++) {
        float o = acc[h] / (s[h] + 1e-16f) + bias[h * 32 + lane];
        o = fmaxf(o, NEG * o);                          // post-layer leaky_relu
        outbuf[n * 128 + h * 32 + lane] = o;
    }
}

// ---------------- pooling ----------------
__global__ void pool_kernel(const float* __restrict__ hbuf, const int* __restrict__ batch) {
    int idx = blockIdx.x * blockDim.x + threadIdx.x;
    if (idx >= NN * HID) return;
    int nnode = idx >> 7, j = idx & 127;
    atomicAdd(&g_pool[batch[nnode] * HID + j], hbuf[idx]);
}

// ---------------- head: out = bn_g * (pool @ fc_w + fc_b)/sqrt(1+eps) + bn_b ----------------
__global__ void head_kernel(const float* __restrict__ fc_w, const float* __restrict__ fc_b,
                            const float* __restrict__ bn_g, const float* __restrict__ bn_b,
                            float* __restrict__ out)
{
    int g = blockIdx.x;
    int l = threadIdx.x;  // 0..31
    const float* pr = g_pool + g * HID;
    float s = 0.f;
#pragma unroll 8
    for (int k = 0; k < HID; k++) s = fmaf(pr[k], fc_w[k * LAT + l], s);
    s += fc_b[l];
    const float inv = 0.999995000037499688f;  // 1/sqrt(1 + 1e-5)
    out[g * LAT + l] = bn_g[l] * s * inv + bn_b[l];
}

// ---------------- launch ----------------
extern "C" void kernel_launch(void* const* d_in, const int* in_sizes, int n_in,
                              void* d_out, int out_size)
{
    const float* x       = (const float*)d_in[0];
    const int*   eidx    = (const int*)  d_in[1];
    const int*   batch   = (const int*)  d_in[2];
    const float* W0      = (const float*)d_in[3];
    const float* a_src0  = (const float*)d_in[4];
    const float* a_dst0  = (const float*)d_in[5];
    const float* b0      = (const float*)d_in[6];
    const float* W1      = (const float*)d_in[7];
    const float* a_src1  = (const float*)d_in[8];
    const float* a_dst1  = (const float*)d_in[9];
    const float* b1      = (const float*)d_in[10];
    const float* W2      = (const float*)d_in[11];
    const float* a_src2  = (const float*)d_in[12];
    const float* a_dst2  = (const float*)d_in[13];
    const float* b2      = (const float*)d_in[14];
    const float* fc_w    = (const float*)d_in[15];
    const float* fc_b    = (const float*)d_in[16];
    const float* bn_g    = (const float*)d_in[17];
    const float* bn_b    = (const float*)d_in[18];
    float* out = (float*)d_out;

    const int* src = eidx;
    const int* dst = eidx + EE;

    float *ph, *py;
    cudaGetSymbolAddress((void**)&ph, g_h);
    cudaGetSymbolAddress((void**)&py, g_y);

    // CSR build (per-launch; graph is static but inputs define it)
    {
        int mx = (NN > GG * HID) ? NN : GG * HID;
        init_kernel<<<(mx + 255) / 256, 256>>>();
        hist_kernel<<<(EE + 255) / 256, 256>>>(dst);
        scan_kernel<<<1, 1024>>>();
        scatter_kernel<<<(EE + NN + 255) / 256, 256>>>(src, dst);
    }

    const int gemm_grid = (NN + 31) / 32;
    const int agg_grid  = (NN + 7) / 8;      // 8 warps / 256-thread block
    const int alp_grid  = (NN + 7) / 8;

    // layer 0: x[N,64] -> h, agg -> y
    gemm_kernel<<<gemm_grid, 256>>>(x, W0, ph, NN, 64);
    alpha_kernel<<<alp_grid, 256>>>(ph, a_src0, a_dst0);
    agg_kernel<<<agg_grid, 256>>>(ph, b0, py);

    // layer 1
    gemm_kernel<<<gemm_grid, 256>>>(py, W1, ph, NN, 128);
    alpha_kernel<<<alp_grid, 256>>>(ph, a_src1, a_dst1);
    agg_kernel<<<agg_grid, 256>>>(ph, b1, py);

    // layer 2
    gemm_kernel<<<gemm_grid, 256>>>(py, W2, ph, NN, 128);
    alpha_kernel<<<alp_grid, 256>>>(ph, a_src2, a_dst2);
    agg_kernel<<<agg_grid, 256>>>(ph, b2, py);

    // pool + head
    pool_kernel<<<(NN * HID + 255) / 256, 256>>>(py, batch);
    head_kernel<<<GG, LAT>>>(fc_w, fc_b, bn_g, bn_b, out);
}

// round 2
// speedup vs baseline: 1.5687x; 1.5687x over previous
#include <cuda_runtime.h>
#include <math.h>

#define NN 50000
#define EE 800000
#define HID 128
#define GG 128
#define LAT 32
#define NEG 0.2f

// ---------------- scratch (static device memory; no allocations) ----------------
__device__ float g_h[NN * HID];      // linear output of current layer (pre-bias)
__device__ float g_y[NN * HID];      // node features (layer output)
__device__ float g_as[NN * 4];       // alpha_src per node/head
__device__ float g_ad[NN * 4];       // alpha_dst per node/head
__device__ int   g_deg[NN];
__device__ int   g_rowoff[NN + 1];
__device__ int   g_cur[NN];
__device__ int   g_csr[EE + NN];     // src node id per incoming edge, grouped by dst
__device__ float g_pool[GG * HID];

// ---------------- CSR build ----------------
__global__ void init_kernel() {
    int i = blockIdx.x * blockDim.x + threadIdx.x;
    if (i < NN) g_deg[i] = 1;                 // self loop
    if (i < GG * HID) g_pool[i] = 0.0f;
}

__global__ void hist_kernel(const int* __restrict__ dst) {
    int i = blockIdx.x * blockDim.x + threadIdx.x;
    if (i < EE) atomicAdd(&g_deg[dst[i]], 1);
}

__global__ void scan_kernel() {
    __shared__ int sums[1024];
    const int T = 1024;
    int t = threadIdx.x;
    const int chunk = (NN + T - 1) / T;
    int start = t * chunk;
    int end = min(start + chunk, NN);
    int s = 0;
    for (int i = start; i < end; i++) s += g_deg[i];
    sums[t] = s;
    __syncthreads();
    for (int off = 1; off < T; off <<= 1) {
        int v = 0;
        if (t >= off) v = sums[t - off];
        __syncthreads();
        if (t >= off) sums[t] += v;
        __syncthreads();
    }
    int base = (t == 0) ? 0 : sums[t - 1];
    for (int i = start; i < end; i++) {
        g_rowoff[i] = base;
        g_cur[i] = base;
        base += g_deg[i];
    }
    if (t == 0) g_rowoff[NN] = sums[T - 1];
}

__global__ void scatter_kernel(const int* __restrict__ src, const int* __restrict__ dst) {
    int i = blockIdx.x * blockDim.x + threadIdx.x;
    if (i < EE) {
        int d = dst[i];
        int pos = atomicAdd(&g_cur[d], 1);
        g_csr[pos] = src[i];
    } else if (i < EE + NN) {
        int n = i - EE;
        int pos = atomicAdd(&g_cur[n], 1);
        g_csr[pos] = n;  // self loop
    }
}

// ---------------- GEMM: Out[n, 128] = X[n, K] @ W[K, 128] ----------------
__global__ __launch_bounds__(256) void gemm_kernel(
    const float* __restrict__ X, const float* __restrict__ W,
    float* __restrict__ Out, int nrows, int K)
{
    __shared__ float Ws[64 * 128];
    __shared__ float xs[32 * 68];
    int tid = threadIdx.x;
    int ty = tid >> 3;
    int tx = tid & 7;
    int row0 = blockIdx.x * 32;
    int row = row0 + ty;

    float4 acc[4];
#pragma unroll
    for (int i = 0; i < 4; i++) acc[i] = make_float4(0.f, 0.f, 0.f, 0.f);

    for (int k0 = 0; k0 < K; k0 += 64) {
        const float4* Wg = (const float4*)(W + k0 * 128);
        float4* Wsv = (float4*)Ws;
        for (int i = tid; i < 64 * 128 / 4; i += 256) Wsv[i] = Wg[i];
        for (int i = tid; i < 32 * 64; i += 256) {
            int r = i >> 6, k = i & 63;
            int gr = row0 + r;
            xs[r * 68 + k] = (gr < nrows) ? X[gr * K + k0 + k] : 0.0f;
        }
        __syncthreads();
#pragma unroll 4
        for (int k = 0; k < 64; k++) {
            float xv = xs[ty * 68 + k];
            const float* wr = Ws + k * 128 + tx * 4;
#pragma unroll
            for (int i = 0; i < 4; i++) {
                float4 w = *(const float4*)(wr + i * 32);
                acc[i].x = fmaf(xv, w.x, acc[i].x);
                acc[i].y = fmaf(xv, w.y, acc[i].y);
                acc[i].z = fmaf(xv, w.z, acc[i].z);
                acc[i].w = fmaf(xv, w.w, acc[i].w);
            }
        }
        __syncthreads();
    }
    if (row < nrows) {
        float4* o = (float4*)(Out + row * 128);
#pragma unroll
        for (int i = 0; i < 4; i++) o[i * 8 + tx] = acc[i];
    }
}

// ---------------- alpha: as[n,h] = <h[n,h,:], a_src[h,:]>, ad likewise ----------------
// Lane l covers head (l>>3), channels (l&7)*4..+3 (float4). 8-lane subgroup reduce.
__global__ __launch_bounds__(256) void alpha_kernel(
    const float* __restrict__ hbuf,
    const float* __restrict__ a_src,
    const float* __restrict__ a_dst)
{
    int n = (blockIdx.x * blockDim.x + threadIdx.x) >> 5;
    if (n >= NN) return;
    int lane = threadIdx.x & 31;
    int head = lane >> 3;
    int col = head * 32 + (lane & 7) * 4;

    float4 hv = *(const float4*)(hbuf + n * 128 + col);
    float4 as4 = *(const float4*)(a_src + col);
    float4 ad4 = *(const float4*)(a_dst + col);
    float s1 = hv.x * as4.x + hv.y * as4.y + hv.z * as4.z + hv.w * as4.w;
    float s2 = hv.x * ad4.x + hv.y * ad4.y + hv.z * ad4.z + hv.w * ad4.w;
#pragma unroll
    for (int off = 4; off; off >>= 1) {
        s1 += __shfl_xor_sync(0xffffffffu, s1, off);
        s2 += __shfl_xor_sync(0xffffffffu, s2, off);
    }
    if ((lane & 7) == 0) {
        g_as[n * 4 + head] = s1;
        g_ad[n * 4 + head] = s2;
    }
}

// ---------------- aggregation: one warp per dst node, two-pass softmax ----------------
// Lane l owns head (l>>3), channels (l&7)*4..+3. Pass 1: edge-parallel max.
// Pass 2: edge-parallel exp (staged in smem), serial branch-free gather-FMA.
__global__ __launch_bounds__(256) void agg_kernel(
    const float* __restrict__ hbuf, const float* __restrict__ bias,
    float* __restrict__ outbuf)
{
    __shared__ int   s_src[8][32];
    __shared__ float4 s_p[8][32];

    int wi = threadIdx.x >> 5;
    int n = (blockIdx.x * blockDim.x + threadIdx.x) >> 5;
    if (n >= NN) return;
    int lane = threadIdx.x & 31;
    int head = lane >> 3;
    int col = head * 32 + (lane & 7) * 4;

    float4 adv = *(const float4*)&g_ad[n * 4];
    int beg = g_rowoff[n], end = g_rowoff[n + 1];

    // ---- pass 1: per-head max over incoming edges (edge-parallel) ----
    float4 mx = make_float4(-1e30f, -1e30f, -1e30f, -1e30f);
    for (int p = beg + lane; p < end; p += 32) {
        int s = __ldg(&g_csr[p]);
        float4 a = __ldg((const float4*)&g_as[s * 4]);
        float e;
        e = a.x + adv.x; mx.x = fmaxf(mx.x, fmaxf(e, NEG * e));
        e = a.y + adv.y; mx.y = fmaxf(mx.y, fmaxf(e, NEG * e));
        e = a.z + adv.z; mx.z = fmaxf(mx.z, fmaxf(e, NEG * e));
        e = a.w + adv.w; mx.w = fmaxf(mx.w, fmaxf(e, NEG * e));
    }
#pragma unroll
    for (int off = 16; off; off >>= 1) {
        mx.x = fmaxf(mx.x, __shfl_xor_sync(0xffffffffu, mx.x, off));
        mx.y = fmaxf(mx.y, __shfl_xor_sync(0xffffffffu, mx.y, off));
        mx.z = fmaxf(mx.z, __shfl_xor_sync(0xffffffffu, mx.z, off));
        mx.w = fmaxf(mx.w, __shfl_xor_sync(0xffffffffu, mx.w, off));
    }

    // ---- pass 2 ----
    float4 acc = make_float4(0.f, 0.f, 0.f, 0.f);
    float4 ss  = make_float4(0.f, 0.f, 0.f, 0.f);

    for (int p0 = beg; p0 < end; p0 += 32) {
        int cnt = min(32, end - p0);
        float4 pv = make_float4(0.f, 0.f, 0.f, 0.f);
        int s = 0;
        if (lane < cnt) {
            s = __ldg(&g_csr[p0 + lane]);
            float4 a = __ldg((const float4*)&g_as[s * 4]);
            float e;
            e = a.x + adv.x; e = fmaxf(e, NEG * e); pv.x = __expf(e - mx.x);
            e = a.y + adv.y; e = fmaxf(e, NEG * e); pv.y = __expf(e - mx.y);
            e = a.z + adv.z; e = fmaxf(e, NEG * e); pv.z = __expf(e - mx.z);
            e = a.w + adv.w; e = fmaxf(e, NEG * e); pv.w = __expf(e - mx.w);
            ss.x += pv.x; ss.y += pv.y; ss.z += pv.z; ss.w += pv.w;
        }
        s_src[wi][lane] = s;
        s_p[wi][lane] = pv;
        __syncwarp();
        for (int j = 0; j < cnt; j++) {
            int sj = s_src[wi][j];
            float pj = ((const float*)&s_p[wi][j])[head];
            float4 hv = __ldg((const float4*)(hbuf + sj * 128 + col));
            acc.x = fmaf(pj, hv.x, acc.x);
            acc.y = fmaf(pj, hv.y, acc.y);
            acc.z = fmaf(pj, hv.z, acc.z);
            acc.w = fmaf(pj, hv.w, acc.w);
        }
        __syncwarp();
    }

    // reduce denominator across warp (per head component)
#pragma unroll
    for (int off = 16; off; off >>= 1) {
        ss.x += __shfl_xor_sync(0xffffffffu, ss.x, off);
        ss.y += __shfl_xor_sync(0xffffffffu, ss.y, off);
        ss.z += __shfl_xor_sync(0xffffffffu, ss.z, off);
        ss.w += __shfl_xor_sync(0xffffffffu, ss.w, off);
    }
    float sh = (head == 0) ? ss.x : (head == 1) ? ss.y : (head == 2) ? ss.z : ss.w;
    float inv = 1.0f / (sh + 1e-16f);

    float4 b = *(const float4*)(bias + col);
    float4 o;
    o.x = acc.x * inv + b.x; o.x = fmaxf(o.x, NEG * o.x);
    o.y = acc.y * inv + b.y; o.y = fmaxf(o.y, NEG * o.y);
    o.z = acc.z * inv + b.z; o.z = fmaxf(o.z, NEG * o.z);
    o.w = acc.w * inv + b.w; o.w = fmaxf(o.w, NEG * o.w);
    *(float4*)(outbuf + n * 128 + col) = o;
}

// ---------------- pooling ----------------
__global__ void pool_kernel(const float* __restrict__ hbuf, const int* __restrict__ batch) {
    int idx = blockIdx.x * blockDim.x + threadIdx.x;
    if (idx >= NN * HID) return;
    int nnode = idx >> 7, j = idx & 127;
    atomicAdd(&g_pool[batch[nnode] * HID + j], hbuf[idx]);
}

// ---------------- head ----------------
__global__ void head_kernel(const float* __restrict__ fc_w, const float* __restrict__ fc_b,
                            const float* __restrict__ bn_g, const float* __restrict__ bn_b,
                            float* __restrict__ out)
{
    int g = blockIdx.x;
    int l = threadIdx.x;  // 0..31
    const float* pr = g_pool + g * HID;
    float s = 0.f;
#pragma unroll 8
    for (int k = 0; k < HID; k++) s = fmaf(pr[k], fc_w[k * LAT + l], s);
    s += fc_b[l];
    const float inv = 0.999995000037499688f;  // 1/sqrt(1 + 1e-5)
    out[g * LAT + l] = bn_g[l] * s * inv + bn_b[l];
}

// ---------------- launch ----------------
extern "C" void kernel_launch(void* const* d_in, const int* in_sizes, int n_in,
                              void* d_out, int out_size)
{
    const float* x       = (const float*)d_in[0];
    const int*   eidx    = (const int*)  d_in[1];
    const int*   batch   = (const int*)  d_in[2];
    const float* W0      = (const float*)d_in[3];
    const float* a_src0  = (const float*)d_in[4];
    const float* a_dst0  = (const float*)d_in[5];
    const float* b0      = (const float*)d_in[6];
    const float* W1      = (const float*)d_in[7];
    const float* a_src1  = (const float*)d_in[8];
    const float* a_dst1  = (const float*)d_in[9];
    const float* b1      = (const float*)d_in[10];
    const float* W2      = (const float*)d_in[11];
    const float* a_src2  = (const float*)d_in[12];
    const float* a_dst2  = (const float*)d_in[13];
    const float* b2      = (const float*)d_in[14];
    const float* fc_w    = (const float*)d_in[15];
    const float* fc_b    = (const float*)d_in[16];
    const float* bn_g    = (const float*)d_in[17];
    const float* bn_b    = (const float*)d_in[18];
    float* out = (float*)d_out;

    const int* src = eidx;
    const int* dst = eidx + EE;

    float *ph, *py;
    cudaGetSymbolAddress((void**)&ph, g_h);
    cudaGetSymbolAddress((void**)&py, g_y);

    {
        int mx = (NN > GG * HID) ? NN : GG * HID;
        init_kernel<<<(mx + 255) / 256, 256>>>();
        hist_kernel<<<(EE + 255) / 256, 256>>>(dst);
        scan_kernel<<<1, 1024>>>();
        scatter_kernel<<<(EE + NN + 255) / 256, 256>>>(src, dst);
    }

    const int gemm_grid = (NN + 31) / 32;
    const int warp_grid = (NN + 7) / 8;      // 8 warps / 256-thread block

    gemm_kernel<<<gemm_grid, 256>>>(x, W0, ph, NN, 64);
    alpha_kernel<<<warp_grid, 256>>>(ph, a_src0, a_dst0);
    agg_kernel<<<warp_grid, 256>>>(ph, b0, py);

    gemm_kernel<<<gemm_grid, 256>>>(py, W1, ph, NN, 128);
    alpha_kernel<<<warp_grid, 256>>>(ph, a_src1, a_dst1);
    agg_kernel<<<warp_grid, 256>>>(ph, b1, py);

    gemm_kernel<<<gemm_grid, 256>>>(py, W2, ph, NN, 128);
    alpha_kernel<<<warp_grid, 256>>>(ph, a_src2, a_dst2);
    agg_kernel<<<warp_grid, 256>>>(ph, b2, py);

    pool_kernel<<<(NN * HID + 255) / 256, 256>>>(py, batch);
    head_kernel<<<GG, LAT>>>(fc_w, fc_b, bn_g, bn_b, out);
}